// round 2
// baseline (speedup 1.0000x reference)
#include <cuda_runtime.h>
#include <math.h>

#define B    2
#define C    64
#define H    192
#define W    192
#define SH   384
#define SW   384
#define NPIX (H*W)     // 36864
#define NOUT (SH*SW)   // 147456

typedef unsigned long long ull;

// ---------------- device scratch ----------------
__device__ float2 d_feat2[C*NPIX];     // feat, batch-packed: [c][pix] -> (b0,b1)
__device__ float  d_wt[3*C*C];         // conv weights transposed: [g][c][o]
__device__ float2 d_wcmix[4*C*8];      // per-class mixed compress, dup-packed
__device__ float2 d_wemix[4*C*8];      // per-class mixed expand, dup-packed
__device__ float  d_offs[8];           // per-class offsets

// ---------------- packed f32x2 helpers ----------------
__device__ __forceinline__ ull fma2(ull a, ull b, ull c){
    ull d; asm("fma.rn.f32x2 %0, %1, %2, %3;" : "=l"(d) : "l"(a), "l"(b), "l"(c)); return d;
}
__device__ __forceinline__ ull mul2(ull a, ull b){
    ull d; asm("mul.rn.f32x2 %0, %1, %2;" : "=l"(d) : "l"(a), "l"(b)); return d;
}
__device__ __forceinline__ ull pk2(float x, float y){
    ull u; asm("mov.b64 %0, {%1, %2};" : "=l"(u) : "f"(x), "f"(y)); return u;
}
__device__ __forceinline__ float2 upk(ull u){
    float2 v; asm("mov.b64 {%0, %1}, %2;" : "=f"(v.x), "=f"(v.y) : "l"(u)); return v;
}

// ============================================================================
// Kernel A: block 0 = 4-parity-class MLP + mixed matrices; blocks 1..12 =
// coalesced weight transpose.
// ============================================================================
__global__ void param_kernel(const float* __restrict__ wce, const float* __restrict__ wee,
                             const float* __restrict__ w1,  const float* __restrict__ b1,
                             const float* __restrict__ w2,  const float* __restrict__ b2,
                             const float* __restrict__ wr,  const float* __restrict__ br,
                             const float* __restrict__ wo,  const float* __restrict__ bo,
                             const float* __restrict__ wcv,
                             const int* __restrict__ scale_p, const int* __restrict__ scale2_p)
{
    int tid = threadIdx.x;   // 256

    if (blockIdx.x > 0) {
        // transpose: read wcv linear (coalesced), scatter to d_wt[g][c][o]
        int base = (blockIdx.x - 1) * 1024;
        #pragma unroll
        for (int k = 0; k < 4; k++) {
            int idx = base + k*256 + tid;          // idx = o*192 + g*64 + c
            int o = idx / 192, r = idx - o*192;
            int g = r >> 6, c = r & 63;
            d_wt[g*4096 + c*64 + o] = wcv[idx];
        }
        return;
    }

    __shared__ float s_emb1[4][64];
    __shared__ float s_emb [4][64];
    __shared__ float s_rout[4][4];
    int cls = tid >> 6, o = tid & 63;
    float sc  = (float)(*scale_p);
    float sc2 = (float)(*scale2_p);

    int ip = cls >> 1, jp = cls & 1;
    float ihv = (ip + 0.5f) / sc;
    float ch  = ihv - floorf(ihv + 0.001f) - 0.5f;
    float iwv = (jp + 0.5f) / sc2;
    float cw  = iwv - floorf(iwv + 0.001f) - 0.5f;
    float i0 = 1.0f / sc2, i1 = 1.0f / sc;

    float z = w1[o*4+0]*i0 + w1[o*4+1]*i1 + w1[o*4+2]*ch + w1[o*4+3]*cw + b1[o];
    s_emb1[cls][o] = fmaxf(z, 0.0f);
    __syncthreads();

    float z2 = b2[o];
    #pragma unroll 8
    for (int j = 0; j < 64; j++) z2 += w2[o*64+j] * s_emb1[cls][j];
    s_emb[cls][o] = fmaxf(z2, 0.0f);
    __syncthreads();

    if (o < 4) {
        float zr = br[o];
        #pragma unroll 8
        for (int j = 0; j < 64; j++) zr += wr[o*64+j] * s_emb[cls][j];
        s_rout[cls][o] = 1.0f / (1.0f + expf(-zr));
    } else if (o < 6) {
        int d = o - 4;
        float zo = bo[d];
        #pragma unroll 8
        for (int j = 0; j < 64; j++) zo += wo[d*64+j] * s_emb[cls][j];
        d_offs[cls*2 + d] = zo;
    }
    __syncthreads();

    for (int idx = tid; idx < 4*512; idx += 256) {
        int cc = idx >> 9, r = idx & 511, c = r >> 3, k = r & 7;
        float r0 = s_rout[cc][0], r1 = s_rout[cc][1], r2 = s_rout[cc][2], r3 = s_rout[cc][3];
        float vc = r0*wce[0*512 + k*64 + c] + r1*wce[1*512 + k*64 + c]
                 + r2*wce[2*512 + k*64 + c] + r3*wce[3*512 + k*64 + c];
        d_wcmix[idx] = make_float2(vc, vc);
        float ve = r0*wee[0*512 + c*8 + k] + r1*wee[1*512 + c*8 + k]
                 + r2*wee[2*512 + c*8 + k] + r3*wee[3*512 + c*8 + k];
        d_wemix[idx] = make_float2(ve, ve);
    }
}

// ============================================================================
// Kernel B: fused Sobel + 1x1 conv (192->64). P=2 pixels/thread so each
// weight LDS.128 feeds 2x the FFMA2s. Tile 16x8, 128 threads, 4 chunks of
// 16 in-channels.
// ============================================================================
__global__ __launch_bounds__(128) void feat_kernel(const float* __restrict__ x,
                                                   const float* __restrict__ bcv)
{
    __shared__ float s_tile[16][180];   // [c8][10 rows x 18 cols halo]
    __shared__ float s_w[16][192];      // [c8][g*64+o]
    int tid = threadIdx.x;
    int slot = tid & 63;                // pixel slot: pixels slot and slot+64
    int half = tid >> 6;
    int obase = half * 32;
    int r0 = slot >> 4;                 // rows 0..3 (pixel1 at r0+4)
    int cx = slot & 15;
    int bx = blockIdx.x * 16, by = blockIdx.y * 8;
    int batch = blockIdx.z;
    const float* xb = x + batch * (C*NPIX);

    ull acc[32];                        // [pix(2)][outpair(16)]
    #pragma unroll
    for (int i = 0; i < 32; i++) acc[i] = 0ULL;

    for (int ccb = 0; ccb < 64; ccb += 16) {
        __syncthreads();
        for (int e = tid; e < 16*180; e += 128) {
            int c8 = e / 180, p = e - c8*180;
            int py = p / 18, px = p - py*18;
            int gy = by + py - 1, gx = bx + px - 1;
            float v = 0.0f;
            if (gy >= 0 && gy < H && gx >= 0 && gx < W)
                v = xb[(ccb + c8)*NPIX + gy*W + gx];
            s_tile[c8][p] = v;
        }
        for (int e = tid; e < 16*192; e += 128) {
            int c8 = e / 192, r = e - c8*192;
            int g = r >> 6, oo = r & 63;
            s_w[c8][r] = d_wt[g*4096 + (ccb + c8)*64 + oo];
        }
        __syncthreads();

        #pragma unroll 1
        for (int c8 = 0; c8 < 16; c8++) {
            const float* t = &s_tile[c8][r0*18 + cx];
            float a00=t[0],  a01=t[1],  a02=t[2];
            float a10=t[18], a11=t[19], a12=t[20];
            float a20=t[36], a21=t[37], a22=t[38];
            const float* u = t + 72;    // pixel1: row r0+4
            float b00=u[0],  b01=u[1],  b02=u[2];
            float b10=u[18], b11=u[19], b12=u[20];
            float b20=u[36], b21=u[37], b22=u[38];

            float va  = a11;
            float gxa = (a02 - a00) + 2.0f*(a12 - a10) + (a22 - a20);
            float gya = (a20 - a00) + 2.0f*(a21 - a01) + (a22 - a02);
            float vb  = b11;
            float gxb = (b02 - b00) + 2.0f*(b12 - b10) + (b22 - b20);
            float gyb = (b20 - b00) + 2.0f*(b21 - b01) + (b22 - b02);

            ull VA = pk2(va, va),  GXA = pk2(gxa, gxa), GYA = pk2(gya, gya);
            ull VB = pk2(vb, vb),  GXB = pk2(gxb, gxb), GYB = pk2(gyb, gyb);

            const ulonglong2* w0p = (const ulonglong2*)&s_w[c8][  0 + obase];
            const ulonglong2* w1p = (const ulonglong2*)&s_w[c8][ 64 + obase];
            const ulonglong2* w2p = (const ulonglong2*)&s_w[c8][128 + obase];
            #pragma unroll
            for (int wg = 0; wg < 8; wg++) {
                ulonglong2 w0 = w0p[wg], w1 = w1p[wg], w2 = w2p[wg];
                acc[wg*2+0]    = fma2(w0.x, VA,  acc[wg*2+0]);
                acc[wg*2+1]    = fma2(w0.y, VA,  acc[wg*2+1]);
                acc[16+wg*2+0] = fma2(w0.x, VB,  acc[16+wg*2+0]);
                acc[16+wg*2+1] = fma2(w0.y, VB,  acc[16+wg*2+1]);
                acc[wg*2+0]    = fma2(w1.x, GXA, acc[wg*2+0]);
                acc[wg*2+1]    = fma2(w1.y, GXA, acc[wg*2+1]);
                acc[16+wg*2+0] = fma2(w1.x, GXB, acc[16+wg*2+0]);
                acc[16+wg*2+1] = fma2(w1.y, GXB, acc[16+wg*2+1]);
                acc[wg*2+0]    = fma2(w2.x, GYA, acc[wg*2+0]);
                acc[wg*2+1]    = fma2(w2.y, GYA, acc[wg*2+1]);
                acc[16+wg*2+0] = fma2(w2.x, GYB, acc[16+wg*2+0]);
                acc[16+wg*2+1] = fma2(w2.y, GYB, acc[16+wg*2+1]);
            }
        }
    }

    int pixA = (by + r0)*W + (bx + cx);
    int pixB = pixA + 4*W;
    float* fout = (float*)d_feat2;
    #pragma unroll
    for (int wg = 0; wg < 8; wg++) {
        #pragma unroll
        for (int hh = 0; hh < 2; hh++) {
            int o0 = obase + wg*4 + hh*2;
            float bi0 = __ldg(&bcv[o0]), bi1 = __ldg(&bcv[o0+1]);
            float2 ra = upk(acc[wg*2 + hh]);
            fout[( o0   *NPIX + pixA)*2 + batch] = ra.x + bi0;
            fout[((o0+1)*NPIX + pixA)*2 + batch] = ra.y + bi1;
            float2 rb = upk(acc[16 + wg*2 + hh]);
            fout[( o0   *NPIX + pixB)*2 + batch] = rb.x + bi0;
            fout[((o0+1)*NPIX + pixB)*2 + batch] = rb.y + bi1;
        }
    }
}

// ============================================================================
// Kernel C: bilinear sample + per-class compress/expand + residual.
// P=2 pixels/thread (j, j+16) — identical class, shared weight LDS and
// shared y-interpolation.
// ============================================================================
__global__ __launch_bounds__(128) void up_kernel(float* __restrict__ out)
{
    __shared__ float2 s_wc[4*512];
    __shared__ float2 s_we[4*512];
    __shared__ float  s_o[8];
    int tid = threadIdx.x;
    for (int e = tid; e < 2048; e += 128) { s_wc[e] = d_wcmix[e]; s_we[e] = d_wemix[e]; }
    if (tid < 8) s_o[tid] = d_offs[tid];
    __syncthreads();

    int jj = tid & 15, ii = tid >> 4;
    int i  = blockIdx.y*8 + ii;
    int j0 = blockIdx.x*32 + jj;
    int j1 = j0 + 16;
    int cls = ((i & 1) << 1) | (j0 & 1);
    float offx = s_o[cls*2+0], offy = s_o[cls*2+1];

    // shared y geometry
    float gy = ((i + 0.5f)*0.5f - 0.5f)*(2.0f/(H-1)) - 1.0f + offy*(2.0f/(H-1));
    float iy = ((gy + 1.0f)*H - 1.0f)*0.5f;
    float y0f = floorf(iy);
    float fy = iy - y0f;
    int y0 = (int)y0f;
    float wy0 = 1.0f - fy, wy1 = fy;
    bool vy0 = (y0   >= 0) && (y0   < H);
    bool vy1 = (y0+1 >= 0) && (y0+1 < H);
    int cy0 = min(max(y0,   0), H-1);
    int cy1 = min(max(y0+1, 0), H-1);

    ull W00[2], W01[2], W10[2], W11[2];
    const ull *P00[2], *P01[2], *P10[2], *P11[2];
    int js[2] = {j0, j1};
    #pragma unroll
    for (int p = 0; p < 2; p++) {
        int j = js[p];
        float gx = ((j + 0.5f)*0.5f - 0.5f)*(2.0f/(W-1)) - 1.0f + offx*(2.0f/(W-1));
        float ix = ((gx + 1.0f)*W - 1.0f)*0.5f;
        float x0f = floorf(ix);
        float fx = ix - x0f;
        int x0 = (int)x0f;
        float wx0 = 1.0f - fx, wx1 = fx;
        bool vx0 = (x0   >= 0) && (x0   < W);
        bool vx1 = (x0+1 >= 0) && (x0+1 < W);
        float w00 = (vx0 && vy0) ? wx0*wy0 : 0.0f;
        float w01 = (vx1 && vy0) ? wx1*wy0 : 0.0f;
        float w10 = (vx0 && vy1) ? wx0*wy1 : 0.0f;
        float w11 = (vx1 && vy1) ? wx1*wy1 : 0.0f;
        int cx0 = min(max(x0,   0), W-1), cx1 = min(max(x0+1, 0), W-1);
        W00[p] = pk2(w00,w00); W01[p] = pk2(w01,w01);
        W10[p] = pk2(w10,w10); W11[p] = pk2(w11,w11);
        P00[p] = (const ull*)(d_feat2 + cy0*W + cx0);
        P01[p] = (const ull*)(d_feat2 + cy0*W + cx1);
        P10[p] = (const ull*)(d_feat2 + cy1*W + cx0);
        P11[p] = (const ull*)(d_feat2 + cy1*W + cx1);
    }

    // pass 1: mid[k] = sum_c wc[c][k] * fea0[c]
    const ulonglong2* wcp = (const ulonglong2*)(s_wc + cls*512);
    ull mid[16];
    #pragma unroll
    for (int k = 0; k < 16; k++) mid[k] = 0ULL;
    #pragma unroll 2
    for (int c = 0; c < 64; c++) {
        ull vA =  mul2(W00[0], P00[0][c*NPIX]);
        vA = fma2(W01[0], P01[0][c*NPIX], vA);
        vA = fma2(W10[0], P10[0][c*NPIX], vA);
        vA = fma2(W11[0], P11[0][c*NPIX], vA);
        ull vB =  mul2(W00[1], P00[1][c*NPIX]);
        vB = fma2(W01[1], P01[1][c*NPIX], vB);
        vB = fma2(W10[1], P10[1][c*NPIX], vB);
        vB = fma2(W11[1], P11[1][c*NPIX], vB);
        #pragma unroll
        for (int kk = 0; kk < 4; kk++) {
            ulonglong2 w = wcp[c*4 + kk];
            mid[kk*2  ]   = fma2(w.x, vA, mid[kk*2  ]);
            mid[kk*2+1]   = fma2(w.y, vA, mid[kk*2+1]);
            mid[8+kk*2  ] = fma2(w.x, vB, mid[8+kk*2  ]);
            mid[8+kk*2+1] = fma2(w.y, vB, mid[8+kk*2+1]);
        }
    }

    // pass 2: out[c] = fea0[c] + sum_k we[c][k] * mid[k]
    const ulonglong2* wep = (const ulonglong2*)(s_we + cls*512);
    float* oA0 = out +          i*SW + j0;
    float* oA1 = out + C*NOUT + i*SW + j0;
    float* oB0 = out +          i*SW + j1;
    float* oB1 = out + C*NOUT + i*SW + j1;
    #pragma unroll 2
    for (int c = 0; c < 64; c++) {
        ull vA =  mul2(W00[0], P00[0][c*NPIX]);
        vA = fma2(W01[0], P01[0][c*NPIX], vA);
        vA = fma2(W10[0], P10[0][c*NPIX], vA);
        vA = fma2(W11[0], P11[0][c*NPIX], vA);
        ull vB =  mul2(W00[1], P00[1][c*NPIX]);
        vB = fma2(W01[1], P01[1][c*NPIX], vB);
        vB = fma2(W10[1], P10[1][c*NPIX], vB);
        vB = fma2(W11[1], P11[1][c*NPIX], vB);
        #pragma unroll
        for (int kk = 0; kk < 4; kk++) {
            ulonglong2 w = wep[c*4 + kk];
            vA = fma2(w.x, mid[kk*2  ],   vA);
            vA = fma2(w.y, mid[kk*2+1],   vA);
            vB = fma2(w.x, mid[8+kk*2  ], vB);
            vB = fma2(w.y, mid[8+kk*2+1], vB);
        }
        float2 rA = upk(vA), rB = upk(vB);
        oA0[c*NOUT] = rA.x;
        oA1[c*NOUT] = rA.y;
        oB0[c*NOUT] = rB.x;
        oB1[c*NOUT] = rB.y;
    }
}

// ============================================================================
extern "C" void kernel_launch(void* const* d_in, const int* in_sizes, int n_in,
                              void* d_out, int out_size)
{
    const float* x   = (const float*)d_in[0];
    const float* wce = (const float*)d_in[1];
    const float* wee = (const float*)d_in[2];
    const float* w1  = (const float*)d_in[3];
    const float* b1  = (const float*)d_in[4];
    const float* w2  = (const float*)d_in[5];
    const float* b2  = (const float*)d_in[6];
    const float* wr  = (const float*)d_in[7];
    const float* br  = (const float*)d_in[8];
    const float* wo  = (const float*)d_in[9];
    const float* bo  = (const float*)d_in[10];
    const float* wcv = (const float*)d_in[11];
    const float* bcv = (const float*)d_in[12];
    const int* scale_p  = (const int*)d_in[13];
    const int* scale2_p = (const int*)d_in[14];
    float* out = (float*)d_out;

    param_kernel<<<13, 256>>>(wce, wee, w1, b1, w2, b2, wr, br, wo, bo, wcv, scale_p, scale2_p);

    dim3 gb(W/16, H/8, B);
    feat_kernel<<<gb, 128>>>(x, bcv);

    dim3 gc(SW/32, SH/8);
    up_kernel<<<gc, 128>>>(out);
}

// round 3
// speedup vs baseline: 1.1502x; 1.1502x over previous
#include <cuda_runtime.h>
#include <math.h>

#define B    2
#define C    64
#define H    192
#define W    192
#define SH   384
#define SW   384
#define NPIX (H*W)     // 36864
#define NOUT (SH*SW)   // 147456

typedef unsigned long long ull;

// ---------------- device scratch ----------------
__device__ float2 d_feat2[C*NPIX];     // feat, batch-packed: [c][pix] -> (b0,b1)
__device__ float  d_wt[3*C*C];         // conv weights transposed: [g][c][o]
__device__ float2 d_wcmix[4*C*8];      // per-class mixed compress, dup-packed [cls][c][k]
__device__ float2 d_wemix[4*C*8];      // per-class mixed expand,   dup-packed [cls][c][k]
__device__ float  d_offs[8];           // per-class offsets

// ---------------- packed f32x2 helpers ----------------
__device__ __forceinline__ ull fma2(ull a, ull b, ull c){
    ull d; asm("fma.rn.f32x2 %0, %1, %2, %3;" : "=l"(d) : "l"(a), "l"(b), "l"(c)); return d;
}
__device__ __forceinline__ ull mul2(ull a, ull b){
    ull d; asm("mul.rn.f32x2 %0, %1, %2;" : "=l"(d) : "l"(a), "l"(b)); return d;
}
__device__ __forceinline__ ull pk2(float x, float y){
    ull u; asm("mov.b64 %0, {%1, %2};" : "=l"(u) : "f"(x), "f"(y)); return u;
}
__device__ __forceinline__ float2 upk(ull u){
    float2 v; asm("mov.b64 {%0, %1}, %2;" : "=f"(v.x), "=f"(v.y) : "l"(u)); return v;
}

// ============================================================================
// Kernel A: block 0 = 4-parity-class MLP + mixed matrices; blocks 1..12 =
// coalesced weight transpose. float4 weight loads to cut latency waves.
// ============================================================================
__global__ void param_kernel(const float* __restrict__ wce, const float* __restrict__ wee,
                             const float* __restrict__ w1,  const float* __restrict__ b1,
                             const float* __restrict__ w2,  const float* __restrict__ b2,
                             const float* __restrict__ wr,  const float* __restrict__ br,
                             const float* __restrict__ wo,  const float* __restrict__ bo,
                             const float* __restrict__ wcv,
                             const int* __restrict__ scale_p, const int* __restrict__ scale2_p)
{
    int tid = threadIdx.x;   // 256

    if (blockIdx.x > 0) {
        int base = (blockIdx.x - 1) * 1024;
        #pragma unroll
        for (int k = 0; k < 4; k++) {
            int idx = base + k*256 + tid;          // idx = o*192 + g*64 + c
            int o = idx / 192, r = idx - o*192;
            int g = r >> 6, c = r & 63;
            d_wt[g*4096 + c*64 + o] = wcv[idx];
        }
        return;
    }

    __shared__ float s_emb1[4][64];
    __shared__ float s_emb [4][64];
    __shared__ float s_rout[4][4];
    int cls = tid >> 6, o = tid & 63;
    float sc  = (float)(*scale_p);
    float sc2 = (float)(*scale2_p);

    int ip = cls >> 1, jp = cls & 1;
    float ihv = (ip + 0.5f) / sc;
    float ch  = ihv - floorf(ihv + 0.001f) - 0.5f;
    float iwv = (jp + 0.5f) / sc2;
    float cw  = iwv - floorf(iwv + 0.001f) - 0.5f;
    float i0 = 1.0f / sc2, i1 = 1.0f / sc;

    float4 w1v = __ldg((const float4*)(w1 + o*4));
    float z = w1v.x*i0 + w1v.y*i1 + w1v.z*ch + w1v.w*cw + b1[o];
    s_emb1[cls][o] = fmaxf(z, 0.0f);
    __syncthreads();

    float z2 = b2[o];
    const float4* w2v = (const float4*)(w2 + o*64);
    #pragma unroll
    for (int j4 = 0; j4 < 16; j4++) {
        float4 wv = __ldg(&w2v[j4]);
        z2 += wv.x*s_emb1[cls][j4*4+0] + wv.y*s_emb1[cls][j4*4+1]
            + wv.z*s_emb1[cls][j4*4+2] + wv.w*s_emb1[cls][j4*4+3];
    }
    s_emb[cls][o] = fmaxf(z2, 0.0f);
    __syncthreads();

    if (o < 4) {
        float zr = br[o];
        const float4* wrv = (const float4*)(wr + o*64);
        #pragma unroll
        for (int j4 = 0; j4 < 16; j4++) {
            float4 wv = __ldg(&wrv[j4]);
            zr += wv.x*s_emb[cls][j4*4+0] + wv.y*s_emb[cls][j4*4+1]
                + wv.z*s_emb[cls][j4*4+2] + wv.w*s_emb[cls][j4*4+3];
        }
        s_rout[cls][o] = 1.0f / (1.0f + expf(-zr));
    } else if (o < 6) {
        int d = o - 4;
        float zo = bo[d];
        const float4* wov = (const float4*)(wo + d*64);
        #pragma unroll
        for (int j4 = 0; j4 < 16; j4++) {
            float4 wv = __ldg(&wov[j4]);
            zo += wv.x*s_emb[cls][j4*4+0] + wv.y*s_emb[cls][j4*4+1]
                + wv.z*s_emb[cls][j4*4+2] + wv.w*s_emb[cls][j4*4+3];
        }
        d_offs[cls*2 + d] = zo;
    }
    __syncthreads();

    // mixed matrices; c fastest for coalesced wce reads; layout stays [cls][c][k]
    for (int idx = tid; idx < 4*512; idx += 256) {
        int cc = idx >> 9, r = idx & 511, c = r & 63, k = r >> 6;
        float r0 = s_rout[cc][0], r1 = s_rout[cc][1], r2 = s_rout[cc][2], r3 = s_rout[cc][3];
        float vc = r0*wce[0*512 + k*64 + c] + r1*wce[1*512 + k*64 + c]
                 + r2*wce[2*512 + k*64 + c] + r3*wce[3*512 + k*64 + c];
        d_wcmix[cc*512 + c*8 + k] = make_float2(vc, vc);
        float ve = r0*wee[0*512 + c*8 + k] + r1*wee[1*512 + c*8 + k]
                 + r2*wee[2*512 + c*8 + k] + r3*wee[3*512 + c*8 + k];
        d_wemix[cc*512 + c*8 + k] = make_float2(ve, ve);
    }
}

// ============================================================================
// Kernel B: fused Sobel + 1x1 conv (192->64). (unchanged from round 2)
// ============================================================================
__global__ __launch_bounds__(128) void feat_kernel(const float* __restrict__ x,
                                                   const float* __restrict__ bcv)
{
    __shared__ float s_tile[16][180];
    __shared__ float s_w[16][192];
    int tid = threadIdx.x;
    int slot = tid & 63;
    int half = tid >> 6;
    int obase = half * 32;
    int r0 = slot >> 4;
    int cx = slot & 15;
    int bx = blockIdx.x * 16, by = blockIdx.y * 8;
    int batch = blockIdx.z;
    const float* xb = x + batch * (C*NPIX);

    ull acc[32];
    #pragma unroll
    for (int i = 0; i < 32; i++) acc[i] = 0ULL;

    for (int ccb = 0; ccb < 64; ccb += 16) {
        __syncthreads();
        for (int e = tid; e < 16*180; e += 128) {
            int c8 = e / 180, p = e - c8*180;
            int py = p / 18, px = p - py*18;
            int gy = by + py - 1, gx = bx + px - 1;
            float v = 0.0f;
            if (gy >= 0 && gy < H && gx >= 0 && gx < W)
                v = xb[(ccb + c8)*NPIX + gy*W + gx];
            s_tile[c8][p] = v;
        }
        for (int e = tid; e < 16*192; e += 128) {
            int c8 = e / 192, r = e - c8*192;
            int g = r >> 6, oo = r & 63;
            s_w[c8][r] = d_wt[g*4096 + (ccb + c8)*64 + oo];
        }
        __syncthreads();

        #pragma unroll 1
        for (int c8 = 0; c8 < 16; c8++) {
            const float* t = &s_tile[c8][r0*18 + cx];
            float a00=t[0],  a01=t[1],  a02=t[2];
            float a10=t[18], a11=t[19], a12=t[20];
            float a20=t[36], a21=t[37], a22=t[38];
            const float* u = t + 72;
            float b00=u[0],  b01=u[1],  b02=u[2];
            float b10=u[18], b11=u[19], b12=u[20];
            float b20=u[36], b21=u[37], b22=u[38];

            float va  = a11;
            float gxa = (a02 - a00) + 2.0f*(a12 - a10) + (a22 - a20);
            float gya = (a20 - a00) + 2.0f*(a21 - a01) + (a22 - a02);
            float vb  = b11;
            float gxb = (b02 - b00) + 2.0f*(b12 - b10) + (b22 - b20);
            float gyb = (b20 - b00) + 2.0f*(b21 - b01) + (b22 - b02);

            ull VA = pk2(va, va),  GXA = pk2(gxa, gxa), GYA = pk2(gya, gya);
            ull VB = pk2(vb, vb),  GXB = pk2(gxb, gxb), GYB = pk2(gyb, gyb);

            const ulonglong2* w0p = (const ulonglong2*)&s_w[c8][  0 + obase];
            const ulonglong2* w1p = (const ulonglong2*)&s_w[c8][ 64 + obase];
            const ulonglong2* w2p = (const ulonglong2*)&s_w[c8][128 + obase];
            #pragma unroll
            for (int wg = 0; wg < 8; wg++) {
                ulonglong2 w0 = w0p[wg], w1 = w1p[wg], w2 = w2p[wg];
                acc[wg*2+0]    = fma2(w0.x, VA,  acc[wg*2+0]);
                acc[wg*2+1]    = fma2(w0.y, VA,  acc[wg*2+1]);
                acc[16+wg*2+0] = fma2(w0.x, VB,  acc[16+wg*2+0]);
                acc[16+wg*2+1] = fma2(w0.y, VB,  acc[16+wg*2+1]);
                acc[wg*2+0]    = fma2(w1.x, GXA, acc[wg*2+0]);
                acc[wg*2+1]    = fma2(w1.y, GXA, acc[wg*2+1]);
                acc[16+wg*2+0] = fma2(w1.x, GXB, acc[16+wg*2+0]);
                acc[16+wg*2+1] = fma2(w1.y, GXB, acc[16+wg*2+1]);
                acc[wg*2+0]    = fma2(w2.x, GYA, acc[wg*2+0]);
                acc[wg*2+1]    = fma2(w2.y, GYA, acc[wg*2+1]);
                acc[16+wg*2+0] = fma2(w2.x, GYB, acc[16+wg*2+0]);
                acc[16+wg*2+1] = fma2(w2.y, GYB, acc[16+wg*2+1]);
            }
        }
    }

    int pixA = (by + r0)*W + (bx + cx);
    int pixB = pixA + 4*W;
    float* fout = (float*)d_feat2;
    #pragma unroll
    for (int wg = 0; wg < 8; wg++) {
        #pragma unroll
        for (int hh = 0; hh < 2; hh++) {
            int o0 = obase + wg*4 + hh*2;
            float bi0 = __ldg(&bcv[o0]), bi1 = __ldg(&bcv[o0+1]);
            float2 ra = upk(acc[wg*2 + hh]);
            fout[( o0   *NPIX + pixA)*2 + batch] = ra.x + bi0;
            fout[((o0+1)*NPIX + pixA)*2 + batch] = ra.y + bi1;
            float2 rb = upk(acc[16 + wg*2 + hh]);
            fout[( o0   *NPIX + pixB)*2 + batch] = rb.x + bi0;
            fout[((o0+1)*NPIX + pixB)*2 + batch] = rb.y + bi1;
        }
    }
}

// ============================================================================
// Kernel C: bilinear sample + per-class compress/expand + residual.
// SINGLE gather pass: fea0 stashed in SMEM (thread-private, no syncs needed),
// pass 2 reads it back. Warps are class-uniform (cls == warp id) so weight
// LDS.128 is a pure broadcast.
// ============================================================================
__global__ __launch_bounds__(128) void up_kernel(float* __restrict__ out)
{
    extern __shared__ char smem_raw[];
    float2* s_wc  = (float2*)smem_raw;          // 2048 float2 = 16KB
    float2* s_we  = s_wc + 2048;                // 16KB
    ull*    s_fea = (ull*)(s_we + 2048);        // 64*128 ull = 64KB
    __shared__ float s_o[8];

    int tid = threadIdx.x;
    for (int e = tid; e < 2048; e += 128) { s_wc[e] = d_wcmix[e]; s_we[e] = d_wemix[e]; }
    if (tid < 8) s_o[tid] = d_offs[tid];
    __syncthreads();

    // class-uniform warp mapping: cls == warp
    int warp = tid >> 5, lane = tid & 31;
    int r = lane >> 3, cc = lane & 7;
    int i = blockIdx.y*8  + r*2 + (warp >> 1);
    int j = blockIdx.x*16 + cc*2 + (warp & 1);
    int cls = warp;
    float offx = s_o[cls*2+0], offy = s_o[cls*2+1];

    float gy = ((i + 0.5f)*0.5f - 0.5f)*(2.0f/(H-1)) - 1.0f + offy*(2.0f/(H-1));
    float iy = ((gy + 1.0f)*H - 1.0f)*0.5f;
    float y0f = floorf(iy);
    float fy = iy - y0f;
    int y0 = (int)y0f;
    float wy0 = 1.0f - fy, wy1 = fy;
    bool vy0 = (y0   >= 0) && (y0   < H);
    bool vy1 = (y0+1 >= 0) && (y0+1 < H);
    int cy0 = min(max(y0,   0), H-1);
    int cy1 = min(max(y0+1, 0), H-1);

    float gx = ((j + 0.5f)*0.5f - 0.5f)*(2.0f/(W-1)) - 1.0f + offx*(2.0f/(W-1));
    float ix = ((gx + 1.0f)*W - 1.0f)*0.5f;
    float x0f = floorf(ix);
    float fx = ix - x0f;
    int x0 = (int)x0f;
    float wx0 = 1.0f - fx, wx1 = fx;
    bool vx0 = (x0   >= 0) && (x0   < W);
    bool vx1 = (x0+1 >= 0) && (x0+1 < W);
    float w00 = (vx0 && vy0) ? wx0*wy0 : 0.0f;
    float w01 = (vx1 && vy0) ? wx1*wy0 : 0.0f;
    float w10 = (vx0 && vy1) ? wx0*wy1 : 0.0f;
    float w11 = (vx1 && vy1) ? wx1*wy1 : 0.0f;
    int cx0 = min(max(x0,   0), W-1), cx1 = min(max(x0+1, 0), W-1);
    ull W00 = pk2(w00,w00), W01 = pk2(w01,w01), W10 = pk2(w10,w10), W11 = pk2(w11,w11);

    const ull* P00 = (const ull*)(d_feat2 + cy0*W + cx0);
    const ull* P01 = (const ull*)(d_feat2 + cy0*W + cx1);
    const ull* P10 = (const ull*)(d_feat2 + cy1*W + cx0);
    const ull* P11 = (const ull*)(d_feat2 + cy1*W + cx1);

    // pass 1: gather fea0 once, stash in SMEM, accumulate mid
    const ulonglong2* wcp = (const ulonglong2*)(s_wc + cls*512);
    ull* fp = s_fea + tid;
    ull mid[8] = {0,0,0,0,0,0,0,0};
    #pragma unroll 4
    for (int c = 0; c < 64; c++) {
        ull v =  mul2(W00, P00[c*NPIX]);
        v = fma2(W01, P01[c*NPIX], v);
        v = fma2(W10, P10[c*NPIX], v);
        v = fma2(W11, P11[c*NPIX], v);
        fp[c*128] = v;
        #pragma unroll
        for (int kk = 0; kk < 4; kk++) {
            ulonglong2 w = wcp[c*4 + kk];
            mid[kk*2  ] = fma2(w.x, v, mid[kk*2  ]);
            mid[kk*2+1] = fma2(w.y, v, mid[kk*2+1]);
        }
    }

    // pass 2: out[c] = fea0[c] + sum_k we[c][k] * mid[k]  (fea0 from SMEM)
    const ulonglong2* wep = (const ulonglong2*)(s_we + cls*512);
    float* o0 = out +          i*SW + j;
    float* o1 = out + C*NOUT + i*SW + j;
    #pragma unroll 4
    for (int c = 0; c < 64; c++) {
        ull v = fp[c*128];
        #pragma unroll
        for (int kk = 0; kk < 4; kk++) {
            ulonglong2 w = wep[c*4 + kk];
            v = fma2(w.x, mid[kk*2  ], v);
            v = fma2(w.y, mid[kk*2+1], v);
        }
        float2 rr = upk(v);
        o0[c*NOUT] = rr.x;
        o1[c*NOUT] = rr.y;
    }
}

// ============================================================================
extern "C" void kernel_launch(void* const* d_in, const int* in_sizes, int n_in,
                              void* d_out, int out_size)
{
    const float* x   = (const float*)d_in[0];
    const float* wce = (const float*)d_in[1];
    const float* wee = (const float*)d_in[2];
    const float* w1  = (const float*)d_in[3];
    const float* b1  = (const float*)d_in[4];
    const float* w2  = (const float*)d_in[5];
    const float* b2  = (const float*)d_in[6];
    const float* wr  = (const float*)d_in[7];
    const float* br  = (const float*)d_in[8];
    const float* wo  = (const float*)d_in[9];
    const float* bo  = (const float*)d_in[10];
    const float* wcv = (const float*)d_in[11];
    const float* bcv = (const float*)d_in[12];
    const int* scale_p  = (const int*)d_in[13];
    const int* scale2_p = (const int*)d_in[14];
    float* out = (float*)d_out;

    static int smem_set = 0;
    if (!smem_set) {
        cudaFuncSetAttribute(up_kernel, cudaFuncAttributeMaxDynamicSharedMemorySize, 98304);
        smem_set = 1;
    }

    param_kernel<<<13, 256>>>(wce, wee, w1, b1, w2, b2, wr, br, wo, bo, wcv, scale_p, scale2_p);

    dim3 gb(W/16, H/8, B);
    feat_kernel<<<gb, 128>>>(x, bcv);

    dim3 gc(SW/16, SH/8);
    up_kernel<<<gc, 128, 98304>>>(out);
}